// round 1
// baseline (speedup 1.0000x reference)
#include <cuda_runtime.h>
#include <math.h>

#define D_MODEL  1024
#define N_HEADS  16
#define HEAD_DIM 64
#define BATCH    2
#define SEQ      2048
#define M_TOT    (BATCH * SEQ)   // 4096

// ---------------- scratch (no allocations allowed) ----------------
__device__ float g_q[M_TOT * D_MODEL];
__device__ float g_k[M_TOT * D_MODEL];
__device__ float g_v[M_TOT * D_MODEL];
__device__ float g_y[M_TOT * D_MODEL];

// =====================================================================
// GEMM: C[m,n] = sum_k X[m,k] * W[n,k] + bias[n]
// (torch Linear semantics: x @ W.T + b ; both operands K-contiguous)
// 64x64 block tile, BK=16, 256 threads, 4x4 per-thread micro-tile.
// =====================================================================
#define BM 64
#define BN 64
#define BK 16

__global__ __launch_bounds__(256) void gemm_xwT_bias(
    const float* __restrict__ X, const float* __restrict__ W,
    const float* __restrict__ bias, float* __restrict__ C,
    int M, int N, int K)
{
    __shared__ __align__(16) float As[BK][BM + 4];
    __shared__ __align__(16) float Bs[BK][BN + 4];

    const int tid = threadIdx.x;
    const int block_m = blockIdx.y * BM;
    const int block_n = blockIdx.x * BN;
    const int tx = tid % 16;       // n-dir
    const int ty = tid / 16;       // m-dir

    const int lrow = tid / 4;            // 0..63
    const int lk4  = (tid % 4) * 4;      // 0,4,8,12

    float acc[4][4] = {};

    const float* xrow = X + (size_t)(block_m + lrow) * K;
    const float* wrow = W + (size_t)(block_n + lrow) * K;

    for (int k0 = 0; k0 < K; k0 += BK) {
        float4 xa = *(const float4*)&xrow[k0 + lk4];
        float4 wb = *(const float4*)&wrow[k0 + lk4];
        As[lk4 + 0][lrow] = xa.x; As[lk4 + 1][lrow] = xa.y;
        As[lk4 + 2][lrow] = xa.z; As[lk4 + 3][lrow] = xa.w;
        Bs[lk4 + 0][lrow] = wb.x; Bs[lk4 + 1][lrow] = wb.y;
        Bs[lk4 + 2][lrow] = wb.z; Bs[lk4 + 3][lrow] = wb.w;
        __syncthreads();

        #pragma unroll
        for (int kk = 0; kk < BK; kk++) {
            float4 a4 = *(const float4*)&As[kk][ty * 4];
            float4 b4 = *(const float4*)&Bs[kk][tx * 4];
            float a[4] = {a4.x, a4.y, a4.z, a4.w};
            float b[4] = {b4.x, b4.y, b4.z, b4.w};
            #pragma unroll
            for (int i = 0; i < 4; i++)
                #pragma unroll
                for (int j = 0; j < 4; j++)
                    acc[i][j] += a[i] * b[j];
        }
        __syncthreads();
    }

    #pragma unroll
    for (int i = 0; i < 4; i++) {
        const int m = block_m + ty * 4 + i;
        float* crow = C + (size_t)m * N + block_n + tx * 4;
        const float* brow = bias + block_n + tx * 4;
        float4 o;
        o.x = acc[i][0] + brow[0];
        o.y = acc[i][1] + brow[1];
        o.z = acc[i][2] + brow[2];
        o.w = acc[i][3] + brow[3];
        *(float4*)crow = o;
    }
}

// =====================================================================
// Flash-style causal attention, fp32.
// Grid: (T/64, B*H). Block: 256 threads.
// Thread (row = tid/4, part = tid%4): owns 16 keys per 64-key block,
// accumulates a PARTIAL O over all 64 dims for its key subset;
// final 4-lane shuffle reduce. No P tile in smem.
// smem: Qs/Ks/Vs each [64][65] fp32 -> 49,920 B (dynamic).
// =====================================================================
#define QB 64
#define KB 64
#define ATTN_SMEM (3 * 64 * 65 * 4)

__global__ __launch_bounds__(256) void attn_kernel(
    const float* __restrict__ Q, const float* __restrict__ K,
    const float* __restrict__ V, float* __restrict__ Y)
{
    extern __shared__ float smem[];
    float* Qs = smem;                  // [64][65]
    float* Ks = smem + 64 * 65;
    float* Vs = smem + 2 * 64 * 65;

    const int bh   = blockIdx.y;
    const int b    = bh / N_HEADS;
    const int h    = bh % N_HEADS;
    const int qblk = blockIdx.x;
    const int tid  = threadIdx.x;
    const int row  = tid / 4;          // query row within tile, 0..63
    const int part = tid % 4;          // key/dim quarter, 0..3

    const size_t base = ((size_t)b * SEQ) * D_MODEL + (size_t)h * HEAD_DIM;

    // load Q tile (float4 from gmem, scalar stores into padded smem)
    #pragma unroll
    for (int r = 0; r < 4; r++) {
        int fi = tid + r * 256;            // 0..1023 float4s
        int qr = fi / 16;
        int c4 = (fi % 16) * 4;
        float4 val = *(const float4*)&Q[base + (size_t)(qblk * QB + qr) * D_MODEL + c4];
        Qs[qr * 65 + c4 + 0] = val.x; Qs[qr * 65 + c4 + 1] = val.y;
        Qs[qr * 65 + c4 + 2] = val.z; Qs[qr * 65 + c4 + 3] = val.w;
    }

    float m_run = -1e30f;
    float l_run = 0.0f;
    float o[HEAD_DIM];
    #pragma unroll
    for (int d = 0; d < HEAD_DIM; d++) o[d] = 0.0f;

    const float scale = 0.125f;            // 1/sqrt(64)
    const int tq = qblk * QB + row;

    for (int kblk = 0; kblk <= qblk; kblk++) {
        __syncthreads();                   // protect Ks/Vs reuse (and Qs on iter 0)
        #pragma unroll
        for (int r = 0; r < 4; r++) {
            int fi = tid + r * 256;
            int kr = fi / 16;
            int c4 = (fi % 16) * 4;
            size_t g = base + (size_t)(kblk * KB + kr) * D_MODEL + c4;
            float4 kv = *(const float4*)&K[g];
            float4 vv = *(const float4*)&V[g];
            Ks[kr * 65 + c4 + 0] = kv.x; Ks[kr * 65 + c4 + 1] = kv.y;
            Ks[kr * 65 + c4 + 2] = kv.z; Ks[kr * 65 + c4 + 3] = kv.w;
            Vs[kr * 65 + c4 + 0] = vv.x; Vs[kr * 65 + c4 + 1] = vv.y;
            Vs[kr * 65 + c4 + 2] = vv.z; Vs[kr * 65 + c4 + 3] = vv.w;
        }
        __syncthreads();

        // S for this thread's 16 keys
        float p[16];
        float smax = -1e30f;
        #pragma unroll
        for (int cc = 0; cc < 16; cc++) {
            const int col = part * 16 + cc;
            float s = 0.0f;
            const float* qr = &Qs[row * 65];
            const float* kr = &Ks[col * 65];
            #pragma unroll
            for (int d = 0; d < 64; d++)
                s += qr[d] * kr[d];
            s *= scale;
            if (kblk * KB + col > tq) s = -1e30f;   // causal mask
            p[cc] = s;
            smax = fmaxf(smax, s);
        }
        // row max across the 4 lanes sharing this row
        smax = fmaxf(smax, __shfl_xor_sync(0xffffffffu, smax, 1));
        smax = fmaxf(smax, __shfl_xor_sync(0xffffffffu, smax, 2));
        const float m_new = fmaxf(m_run, smax);
        const float corr  = __expf(m_run - m_new);

        float lsum = 0.0f;
        #pragma unroll
        for (int cc = 0; cc < 16; cc++) {
            p[cc] = __expf(p[cc] - m_new);
            lsum += p[cc];
        }
        lsum += __shfl_xor_sync(0xffffffffu, lsum, 1);
        lsum += __shfl_xor_sync(0xffffffffu, lsum, 2);
        l_run = l_run * corr + lsum;
        m_run = m_new;

        #pragma unroll
        for (int d = 0; d < HEAD_DIM; d++) o[d] *= corr;

        // partial O over this thread's 16 keys, all 64 dims
        #pragma unroll
        for (int cc = 0; cc < 16; cc++) {
            const float pv = p[cc];
            const float* vr = &Vs[(part * 16 + cc) * 65];
            #pragma unroll
            for (int d = 0; d < HEAD_DIM; d++)
                o[d] += pv * vr[d];
        }
    }

    // reduce partial O across the 4 lanes of this row
    #pragma unroll
    for (int d = 0; d < HEAD_DIM; d++) {
        o[d] += __shfl_xor_sync(0xffffffffu, o[d], 1);
        o[d] += __shfl_xor_sync(0xffffffffu, o[d], 2);
    }
    const float inv_l = 1.0f / l_run;

    // each lane writes its 16 contiguous dims as float4s
    float* yrow = &((float*)Y)[base + (size_t)tq * D_MODEL + part * 16];
    #pragma unroll
    for (int j4 = 0; j4 < 4; j4++) {
        float4 ov;
        ov.x = o[part * 16 + j4 * 4 + 0] * inv_l;
        ov.y = o[part * 16 + j4 * 4 + 1] * inv_l;
        ov.z = o[part * 16 + j4 * 4 + 2] * inv_l;
        ov.w = o[part * 16 + j4 * 4 + 3] * inv_l;
        *(float4*)&yrow[j4 * 4] = ov;
    }
}

// =====================================================================
// launch
// =====================================================================
extern "C" void kernel_launch(void* const* d_in, const int* in_sizes, int n_in,
                              void* d_out, int out_size)
{
    const float* x  = (const float*)d_in[0];
    const float* Wq = (const float*)d_in[1];
    const float* bq = (const float*)d_in[2];
    const float* Wk = (const float*)d_in[3];
    const float* bk = (const float*)d_in[4];
    const float* Wv = (const float*)d_in[5];
    const float* bv = (const float*)d_in[6];
    const float* Wp = (const float*)d_in[7];
    const float* bp = (const float*)d_in[8];
    float* out = (float*)d_out;

    float *q, *k, *v, *y;
    cudaGetSymbolAddress((void**)&q, g_q);
    cudaGetSymbolAddress((void**)&k, g_k);
    cudaGetSymbolAddress((void**)&v, g_v);
    cudaGetSymbolAddress((void**)&y, g_y);

    cudaFuncSetAttribute(attn_kernel,
                         cudaFuncAttributeMaxDynamicSharedMemorySize, ATTN_SMEM);

    dim3 ggrid(D_MODEL / BN, M_TOT / BM);   // (16, 64)
    gemm_xwT_bias<<<ggrid, 256>>>(x, Wq, bq, q, M_TOT, D_MODEL, D_MODEL);
    gemm_xwT_bias<<<ggrid, 256>>>(x, Wk, bk, k, M_TOT, D_MODEL, D_MODEL);
    gemm_xwT_bias<<<ggrid, 256>>>(x, Wv, bv, v, M_TOT, D_MODEL, D_MODEL);

    attn_kernel<<<dim3(SEQ / QB, BATCH * N_HEADS), 256, ATTN_SMEM>>>(q, k, v, y);

    gemm_xwT_bias<<<ggrid, 256>>>(y, Wp, bp, out, M_TOT, D_MODEL, D_MODEL);
}

// round 2
// speedup vs baseline: 1.0010x; 1.0010x over previous
#include <cuda_runtime.h>
#include <math.h>

#define D_MODEL  1024
#define N_HEADS  16
#define HEAD_DIM 64
#define BATCH    2
#define SEQ      2048
#define M_TOT    (BATCH * SEQ)   // 4096

// ---------------- scratch (no allocations allowed) ----------------
__device__ float g_q[M_TOT * D_MODEL];
__device__ float g_k[M_TOT * D_MODEL];
__device__ float g_v[M_TOT * D_MODEL];
__device__ float g_y[M_TOT * D_MODEL];

// =====================================================================
// GEMM: C[m,n] = sum_k X[m,k] * W[n,k] + bias[n]
// (torch Linear semantics: x @ W.T + b ; both operands K-contiguous)
// 64x64 block tile, BK=16, 256 threads, 4x4 per-thread micro-tile.
// =====================================================================
#define BM 64
#define BN 64
#define BK 16

__global__ __launch_bounds__(256) void gemm_xwT_bias(
    const float* __restrict__ X, const float* __restrict__ W,
    const float* __restrict__ bias, float* __restrict__ C,
    int M, int N, int K)
{
    __shared__ __align__(16) float As[BK][BM + 4];
    __shared__ __align__(16) float Bs[BK][BN + 4];

    const int tid = threadIdx.x;
    const int block_m = blockIdx.y * BM;
    const int block_n = blockIdx.x * BN;
    const int tx = tid % 16;       // n-dir
    const int ty = tid / 16;       // m-dir

    const int lrow = tid / 4;            // 0..63
    const int lk4  = (tid % 4) * 4;      // 0,4,8,12

    float acc[4][4] = {};

    const float* xrow = X + (size_t)(block_m + lrow) * K;
    const float* wrow = W + (size_t)(block_n + lrow) * K;

    for (int k0 = 0; k0 < K; k0 += BK) {
        float4 xa = *(const float4*)&xrow[k0 + lk4];
        float4 wb = *(const float4*)&wrow[k0 + lk4];
        As[lk4 + 0][lrow] = xa.x; As[lk4 + 1][lrow] = xa.y;
        As[lk4 + 2][lrow] = xa.z; As[lk4 + 3][lrow] = xa.w;
        Bs[lk4 + 0][lrow] = wb.x; Bs[lk4 + 1][lrow] = wb.y;
        Bs[lk4 + 2][lrow] = wb.z; Bs[lk4 + 3][lrow] = wb.w;
        __syncthreads();

        #pragma unroll
        for (int kk = 0; kk < BK; kk++) {
            float4 a4 = *(const float4*)&As[kk][ty * 4];
            float4 b4 = *(const float4*)&Bs[kk][tx * 4];
            float a[4] = {a4.x, a4.y, a4.z, a4.w};
            float b[4] = {b4.x, b4.y, b4.z, b4.w};
            #pragma unroll
            for (int i = 0; i < 4; i++)
                #pragma unroll
                for (int j = 0; j < 4; j++)
                    acc[i][j] += a[i] * b[j];
        }
        __syncthreads();
    }

    #pragma unroll
    for (int i = 0; i < 4; i++) {
        const int m = block_m + ty * 4 + i;
        float* crow = C + (size_t)m * N + block_n + tx * 4;
        const float* brow = bias + block_n + tx * 4;
        float4 o;
        o.x = acc[i][0] + brow[0];
        o.y = acc[i][1] + brow[1];
        o.z = acc[i][2] + brow[2];
        o.w = acc[i][3] + brow[3];
        *(float4*)crow = o;
    }
}

// =====================================================================
// Flash-style causal attention, fp32.
// Grid: (T/64, B*H). Block: 256 threads.
// Thread (row = tid/4, part = tid%4): owns 16 keys per 64-key block,
// accumulates a PARTIAL O over all 64 dims for its key subset;
// final 4-lane shuffle reduce. No P tile in smem.
// smem: Qs/Ks/Vs each [64][65] fp32 -> 49,920 B (dynamic).
// =====================================================================
#define QB 64
#define KB 64
#define ATTN_SMEM (3 * 64 * 65 * 4)

__global__ __launch_bounds__(256) void attn_kernel(
    const float* __restrict__ Q, const float* __restrict__ K,
    const float* __restrict__ V, float* __restrict__ Y)
{
    extern __shared__ float smem[];
    float* Qs = smem;                  // [64][65]
    float* Ks = smem + 64 * 65;
    float* Vs = smem + 2 * 64 * 65;

    const int bh   = blockIdx.y;
    const int b    = bh / N_HEADS;
    const int h    = bh % N_HEADS;
    const int qblk = blockIdx.x;
    const int tid  = threadIdx.x;
    const int row  = tid / 4;          // query row within tile, 0..63
    const int part = tid % 4;          // key/dim quarter, 0..3

    const size_t base = ((size_t)b * SEQ) * D_MODEL + (size_t)h * HEAD_DIM;

    // load Q tile (float4 from gmem, scalar stores into padded smem)
    #pragma unroll
    for (int r = 0; r < 4; r++) {
        int fi = tid + r * 256;            // 0..1023 float4s
        int qr = fi / 16;
        int c4 = (fi % 16) * 4;
        float4 val = *(const float4*)&Q[base + (size_t)(qblk * QB + qr) * D_MODEL + c4];
        Qs[qr * 65 + c4 + 0] = val.x; Qs[qr * 65 + c4 + 1] = val.y;
        Qs[qr * 65 + c4 + 2] = val.z; Qs[qr * 65 + c4 + 3] = val.w;
    }

    float m_run = -1e30f;
    float l_run = 0.0f;
    float o[HEAD_DIM];
    #pragma unroll
    for (int d = 0; d < HEAD_DIM; d++) o[d] = 0.0f;

    const float scale = 0.125f;            // 1/sqrt(64)
    const int tq = qblk * QB + row;

    for (int kblk = 0; kblk <= qblk; kblk++) {
        __syncthreads();                   // protect Ks/Vs reuse (and Qs on iter 0)
        #pragma unroll
        for (int r = 0; r < 4; r++) {
            int fi = tid + r * 256;
            int kr = fi / 16;
            int c4 = (fi % 16) * 4;
            size_t g = base + (size_t)(kblk * KB + kr) * D_MODEL + c4;
            float4 kv = *(const float4*)&K[g];
            float4 vv = *(const float4*)&V[g];
            Ks[kr * 65 + c4 + 0] = kv.x; Ks[kr * 65 + c4 + 1] = kv.y;
            Ks[kr * 65 + c4 + 2] = kv.z; Ks[kr * 65 + c4 + 3] = kv.w;
            Vs[kr * 65 + c4 + 0] = vv.x; Vs[kr * 65 + c4 + 1] = vv.y;
            Vs[kr * 65 + c4 + 2] = vv.z; Vs[kr * 65 + c4 + 3] = vv.w;
        }
        __syncthreads();

        // S for this thread's 16 keys
        float p[16];
        float smax = -1e30f;
        #pragma unroll
        for (int cc = 0; cc < 16; cc++) {
            const int col = part * 16 + cc;
            float s = 0.0f;
            const float* qr = &Qs[row * 65];
            const float* kr = &Ks[col * 65];
            #pragma unroll
            for (int d = 0; d < 64; d++)
                s += qr[d] * kr[d];
            s *= scale;
            if (kblk * KB + col > tq) s = -1e30f;   // causal mask
            p[cc] = s;
            smax = fmaxf(smax, s);
        }
        // row max across the 4 lanes sharing this row
        smax = fmaxf(smax, __shfl_xor_sync(0xffffffffu, smax, 1));
        smax = fmaxf(smax, __shfl_xor_sync(0xffffffffu, smax, 2));
        const float m_new = fmaxf(m_run, smax);
        const float corr  = __expf(m_run - m_new);

        float lsum = 0.0f;
        #pragma unroll
        for (int cc = 0; cc < 16; cc++) {
            p[cc] = __expf(p[cc] - m_new);
            lsum += p[cc];
        }
        lsum += __shfl_xor_sync(0xffffffffu, lsum, 1);
        lsum += __shfl_xor_sync(0xffffffffu, lsum, 2);
        l_run = l_run * corr + lsum;
        m_run = m_new;

        #pragma unroll
        for (int d = 0; d < HEAD_DIM; d++) o[d] *= corr;

        // partial O over this thread's 16 keys, all 64 dims
        #pragma unroll
        for (int cc = 0; cc < 16; cc++) {
            const float pv = p[cc];
            const float* vr = &Vs[(part * 16 + cc) * 65];
            #pragma unroll
            for (int d = 0; d < HEAD_DIM; d++)
                o[d] += pv * vr[d];
        }
    }

    // reduce partial O across the 4 lanes of this row
    #pragma unroll
    for (int d = 0; d < HEAD_DIM; d++) {
        o[d] += __shfl_xor_sync(0xffffffffu, o[d], 1);
        o[d] += __shfl_xor_sync(0xffffffffu, o[d], 2);
    }
    const float inv_l = 1.0f / l_run;

    // each lane writes its 16 contiguous dims as float4s
    float* yrow = &((float*)Y)[base + (size_t)tq * D_MODEL + part * 16];
    #pragma unroll
    for (int j4 = 0; j4 < 4; j4++) {
        float4 ov;
        ov.x = o[part * 16 + j4 * 4 + 0] * inv_l;
        ov.y = o[part * 16 + j4 * 4 + 1] * inv_l;
        ov.z = o[part * 16 + j4 * 4 + 2] * inv_l;
        ov.w = o[part * 16 + j4 * 4 + 3] * inv_l;
        *(float4*)&yrow[j4 * 4] = ov;
    }
}

// =====================================================================
// launch
// =====================================================================
extern "C" void kernel_launch(void* const* d_in, const int* in_sizes, int n_in,
                              void* d_out, int out_size)
{
    const float* x  = (const float*)d_in[0];
    const float* Wq = (const float*)d_in[1];
    const float* bq = (const float*)d_in[2];
    const float* Wk = (const float*)d_in[3];
    const float* bk = (const float*)d_in[4];
    const float* Wv = (const float*)d_in[5];
    const float* bv = (const float*)d_in[6];
    const float* Wp = (const float*)d_in[7];
    const float* bp = (const float*)d_in[8];
    float* out = (float*)d_out;

    float *q, *k, *v, *y;
    cudaGetSymbolAddress((void**)&q, g_q);
    cudaGetSymbolAddress((void**)&k, g_k);
    cudaGetSymbolAddress((void**)&v, g_v);
    cudaGetSymbolAddress((void**)&y, g_y);

    cudaFuncSetAttribute(attn_kernel,
                         cudaFuncAttributeMaxDynamicSharedMemorySize, ATTN_SMEM);

    dim3 ggrid(D_MODEL / BN, M_TOT / BM);   // (16, 64)
    gemm_xwT_bias<<<ggrid, 256>>>(x, Wq, bq, q, M_TOT, D_MODEL, D_MODEL);
    gemm_xwT_bias<<<ggrid, 256>>>(x, Wk, bk, k, M_TOT, D_MODEL, D_MODEL);
    gemm_xwT_bias<<<ggrid, 256>>>(x, Wv, bv, v, M_TOT, D_MODEL, D_MODEL);

    attn_kernel<<<dim3(SEQ / QB, BATCH * N_HEADS), 256, ATTN_SMEM>>>(q, k, v, y);

    gemm_xwT_bias<<<ggrid, 256>>>(y, Wp, bp, out, M_TOT, D_MODEL, D_MODEL);
}

// round 4
// speedup vs baseline: 3.5364x; 3.5330x over previous
#include <cuda_runtime.h>
#include <cuda_bf16.h>
#include <cstdint>

#define D_MODEL  1024
#define N_HEADS  16
#define HEAD_DIM 64
#define BATCH    2
#define SEQ      2048
#define M_TOT    (BATCH * SEQ)   // 4096

// ---------------- scratch ----------------
__device__ __align__(1024) float g_q[M_TOT * D_MODEL];
__device__ __align__(1024) float g_k[M_TOT * D_MODEL];
__device__ __align__(1024) float g_v[M_TOT * D_MODEL];
__device__ __align__(1024) float g_y[M_TOT * D_MODEL];
__device__ __align__(1024) __nv_bfloat16 g_xhi[M_TOT * D_MODEL];
__device__ __align__(1024) __nv_bfloat16 g_xlo[M_TOT * D_MODEL];
__device__ __align__(1024) __nv_bfloat16 g_yhi[M_TOT * D_MODEL];
__device__ __align__(1024) __nv_bfloat16 g_ylo[M_TOT * D_MODEL];
__device__ __align__(1024) __nv_bfloat16 g_whi[4u * D_MODEL * D_MODEL];
__device__ __align__(1024) __nv_bfloat16 g_wlo[4u * D_MODEL * D_MODEL];

// ---------------- helpers ----------------
__device__ __forceinline__ uint32_t smem_u32(const void* p) {
    uint32_t a;
    asm("{ .reg .u64 t; cvta.to.shared.u64 t, %1; cvt.u32.u64 %0, t; }" : "=r"(a) : "l"(p));
    return a;
}
__device__ __forceinline__ uint32_t swz128(uint32_t off) { return off ^ ((off >> 3) & 0x70); }
__device__ __forceinline__ void cp16(uint32_t s, const void* g) {
    asm volatile("cp.async.cg.shared.global [%0], [%1], 16;" :: "r"(s), "l"(g));
}
#define CP_COMMIT() asm volatile("cp.async.commit_group;" ::: "memory")
#define CP_WAIT(n)  asm volatile("cp.async.wait_group %0;" :: "n"(n) : "memory")

__device__ __forceinline__ void ldsm4(uint32_t r[4], uint32_t addr) {
    asm volatile("ldmatrix.sync.aligned.m8n8.x4.shared.b16 {%0,%1,%2,%3}, [%4];"
                 : "=r"(r[0]), "=r"(r[1]), "=r"(r[2]), "=r"(r[3]) : "r"(addr));
}
__device__ __forceinline__ void mma_bf16(float d[4], const uint32_t a[4], const uint32_t b[2]) {
    asm volatile(
        "mma.sync.aligned.m16n8k16.row.col.f32.bf16.bf16.f32 "
        "{%0,%1,%2,%3}, {%4,%5,%6,%7}, {%8,%9}, {%0,%1,%2,%3};"
        : "+f"(d[0]), "+f"(d[1]), "+f"(d[2]), "+f"(d[3])
        : "r"(a[0]), "r"(a[1]), "r"(a[2]), "r"(a[3]), "r"(b[0]), "r"(b[1]));
}

// ---------------- split fp32 -> bf16 hi/lo ----------------
__global__ __launch_bounds__(256) void split_kernel(
    const float4* __restrict__ x, __nv_bfloat162* __restrict__ hi,
    __nv_bfloat162* __restrict__ lo, int n4)
{
    int i = blockIdx.x * 256 + threadIdx.x;
    if (i >= n4) return;
    float4 v = x[i];
    __nv_bfloat16 h0 = __float2bfloat16(v.x), h1 = __float2bfloat16(v.y);
    __nv_bfloat16 h2 = __float2bfloat16(v.z), h3 = __float2bfloat16(v.w);
    hi[2 * i + 0] = __halves2bfloat162(h0, h1);
    hi[2 * i + 1] = __halves2bfloat162(h2, h3);
    lo[2 * i + 0] = __halves2bfloat162(
        __float2bfloat16(v.x - __bfloat162float(h0)),
        __float2bfloat16(v.y - __bfloat162float(h1)));
    lo[2 * i + 1] = __halves2bfloat162(
        __float2bfloat16(v.z - __bfloat162float(h2)),
        __float2bfloat16(v.w - __bfloat162float(h3)));
}

// ---------------- HMMA split-bf16 GEMM ----------------
// C[m,n] = sum_k (Ahi+Alo)[m,k]*(Bhi+Blo)[n,k] + bias[n]   (lo*lo dropped)
// CTA 128x128, BK=64 bf16 (128B rows, SW128), double-buffered cp.async.
#define T_B    16384                  // one 128x64 bf16 tile
#define STG_B  (4 * T_B)
#define GEMM_SMEM (2 * STG_B)         // 131072
#define KCHUNKS (D_MODEL / 64)        // 16

__device__ __forceinline__ void load_stage(
    uint32_t sbase, const __nv_bfloat16* a0, const __nv_bfloat16* a1,
    const __nv_bfloat16* b0, const __nv_bfloat16* b1, int kc, int tid)
{
    const __nv_bfloat16* gs[4] = {a0, a1, b0, b1};
    #pragma unroll
    for (int t = 0; t < 4; t++) {
        uint32_t tb = sbase + t * T_B;
        const __nv_bfloat16* g = gs[t] + kc * 64;
        #pragma unroll
        for (int i = 0; i < 4; i++) {
            int u = i * 256 + tid;            // 0..1023 16B-chunks
            int r = u >> 3, c8 = u & 7;
            cp16(tb + swz128(r * 128 + c8 * 16), g + (size_t)r * D_MODEL + c8 * 8);
        }
    }
}

__global__ __launch_bounds__(256) void gemm_hmma(
    const __nv_bfloat16* __restrict__ Ahi, const __nv_bfloat16* __restrict__ Alo,
    const __nv_bfloat16* __restrict__ Bhi, const __nv_bfloat16* __restrict__ Blo,
    const float* __restrict__ bias, float* __restrict__ C)
{
    extern __shared__ __align__(1024) char smem[];
    const uint32_t sb = smem_u32(smem);
    const int tid = threadIdx.x;
    const int wid = tid >> 5, lane = tid & 31;
    const int n0 = blockIdx.x * 128, m0 = blockIdx.y * 128;
    const int wm = (wid >> 1) * 32;   // warp m offset (4 warps in m)
    const int wn = (wid & 1) * 64;    // warp n offset (2 warps in n)
    const int gid = lane >> 2, tig = lane & 3;

    const __nv_bfloat16* a0 = Ahi + (size_t)m0 * D_MODEL;
    const __nv_bfloat16* a1 = Alo + (size_t)m0 * D_MODEL;
    const __nv_bfloat16* b0 = Bhi + (size_t)n0 * D_MODEL;
    const __nv_bfloat16* b1 = Blo + (size_t)n0 * D_MODEL;

    // ldmatrix lane geometry
    const int a_row  = wm + (lane & 15);                       // + am*16
    const int a_byte = ((lane >> 4) & 1) * 16;                 // + ks*32
    const int b_row  = wn + ((lane >> 4) & 1) * 8 + (lane & 7); // + pr*16
    const int b_byte = ((lane >> 3) & 1) * 16;                 // + ks*32

    float d[2][8][4];
    #pragma unroll
    for (int i = 0; i < 2; i++)
        #pragma unroll
        for (int j = 0; j < 8; j++)
            #pragma unroll
            for (int c = 0; c < 4; c++) d[i][j][c] = 0.0f;

    load_stage(sb, a0, a1, b0, b1, 0, tid);
    CP_COMMIT();

    for (int kc = 0; kc < KCHUNKS; kc++) {
        const uint32_t st = sb + (kc & 1) * STG_B;
        __syncthreads();                       // prev compute done with other buffer
        if (kc + 1 < KCHUNKS) {
            load_stage(sb + ((kc + 1) & 1) * STG_B, a0, a1, b0, b1, kc + 1, tid);
            CP_COMMIT();
            CP_WAIT(1);
        } else {
            CP_WAIT(0);
        }
        __syncthreads();                       // stage kc visible to all

        #pragma unroll
        for (int ks = 0; ks < 4; ks++) {
            uint32_t ah[2][4], al[2][4];
            #pragma unroll
            for (int am = 0; am < 2; am++) {
                uint32_t off = swz128((uint32_t)(a_row + am * 16) * 128 + a_byte + ks * 32);
                ldsm4(ah[am], st + off);
                ldsm4(al[am], st + T_B + off);
            }
            uint32_t bh[8][2], bl[8][2];
            #pragma unroll
            for (int pr = 0; pr < 4; pr++) {
                uint32_t off = swz128((uint32_t)(b_row + pr * 16) * 128 + b_byte + ks * 32);
                uint32_t r[4];
                ldsm4(r, st + 2 * T_B + off);
                bh[2 * pr][0] = r[0]; bh[2 * pr][1] = r[1];
                bh[2 * pr + 1][0] = r[2]; bh[2 * pr + 1][1] = r[3];
                ldsm4(r, st + 3 * T_B + off);
                bl[2 * pr][0] = r[0]; bl[2 * pr][1] = r[1];
                bl[2 * pr + 1][0] = r[2]; bl[2 * pr + 1][1] = r[3];
            }
            #pragma unroll
            for (int am = 0; am < 2; am++)
                #pragma unroll
                for (int bn = 0; bn < 8; bn++) {
                    mma_bf16(d[am][bn], ah[am], bh[bn]);
                    mma_bf16(d[am][bn], ah[am], bl[bn]);
                    mma_bf16(d[am][bn], al[am], bh[bn]);
                }
        }
    }

    // epilogue: bias + store
    #pragma unroll
    for (int am = 0; am < 2; am++) {
        const int row = m0 + wm + am * 16 + gid;
        #pragma unroll
        for (int bn = 0; bn < 8; bn++) {
            const int col = n0 + wn + bn * 8 + tig * 2;
            const float bv0 = __ldg(&bias[col]);
            const float bv1 = __ldg(&bias[col + 1]);
            float2 o0 = make_float2(d[am][bn][0] + bv0, d[am][bn][1] + bv1);
            float2 o1 = make_float2(d[am][bn][2] + bv0, d[am][bn][3] + bv1);
            *(float2*)&C[(size_t)row * D_MODEL + col] = o0;
            *(float2*)&C[(size_t)(row + 8) * D_MODEL + col] = o1;
        }
    }
}

// ---------------- attention: register-blocked 4x4 FFMA flash ----------------
#define PAD 68
#define ATTN_SMEM (4 * 64 * PAD * 4)   // Qt, Kt, Vs, Ps = 69,632 B

__global__ __launch_bounds__(256) void attn_v2(
    const float* __restrict__ Q, const float* __restrict__ K,
    const float* __restrict__ V, float* __restrict__ Y)
{
    extern __shared__ float sm[];
    float* Qt = sm;                    // [d][q]
    float* Kt = sm + 64 * PAD;         // [d][k]
    float* Vs = sm + 2 * 64 * PAD;     // [k][d]
    float* Ps = sm + 3 * 64 * PAD;     // [k][q]  (P^T)

    const int bh = blockIdx.y;
    const int b = bh >> 4, h = bh & 15;
    const int qblk = blockIdx.x;
    const int tid = threadIdx.x;
    const int tx = tid & 15;
    const int ty = tid >> 4;
    const size_t base = ((size_t)b * SEQ) * D_MODEL + (size_t)h * HEAD_DIM;

    #pragma unroll
    for (int r = 0; r < 4; r++) {
        int fi = tid + r * 256;
        int qr = fi >> 4, c4 = (fi & 15) * 4;
        float4 v = *(const float4*)&Q[base + (size_t)(qblk * 64 + qr) * D_MODEL + c4];
        Qt[(c4 + 0) * PAD + qr] = v.x; Qt[(c4 + 1) * PAD + qr] = v.y;
        Qt[(c4 + 2) * PAD + qr] = v.z; Qt[(c4 + 3) * PAD + qr] = v.w;
    }

    float m_run[4], l_run[4], o[4][4];
    #pragma unroll
    for (int i = 0; i < 4; i++) {
        m_run[i] = -1e30f; l_run[i] = 0.0f;
        #pragma unroll
        for (int j = 0; j < 4; j++) o[i][j] = 0.0f;
    }
    const float scale = 0.125f;

    for (int kblk = 0; kblk <= qblk; kblk++) {
        __syncthreads();
        #pragma unroll
        for (int r = 0; r < 4; r++) {
            int fi = tid + r * 256;
            int kr = fi >> 4, c4 = (fi & 15) * 4;
            size_t g = base + (size_t)(kblk * 64 + kr) * D_MODEL + c4;
            float4 kv = *(const float4*)&K[g];
            Kt[(c4 + 0) * PAD + kr] = kv.x; Kt[(c4 + 1) * PAD + kr] = kv.y;
            Kt[(c4 + 2) * PAD + kr] = kv.z; Kt[(c4 + 3) * PAD + kr] = kv.w;
            *(float4*)&Vs[kr * PAD + c4] = *(const float4*)&V[g];
        }
        __syncthreads();

        float acc[4][4] = {};
        #pragma unroll 16
        for (int dd = 0; dd < 64; dd++) {
            float4 a4 = *(const float4*)&Qt[dd * PAD + ty * 4];
            float4 b4 = *(const float4*)&Kt[dd * PAD + tx * 4];
            float a[4] = {a4.x, a4.y, a4.z, a4.w};
            float bb[4] = {b4.x, b4.y, b4.z, b4.w};
            #pragma unroll
            for (int i = 0; i < 4; i++)
                #pragma unroll
                for (int j = 0; j < 4; j++)
                    acc[i][j] += a[i] * bb[j];
        }
        if (kblk == qblk) {
            #pragma unroll
            for (int i = 0; i < 4; i++)
                #pragma unroll
                for (int j = 0; j < 4; j++) {
                    acc[i][j] *= scale;
                    if (tx * 4 + j > ty * 4 + i) acc[i][j] = -1e30f;
                }
        } else {
            #pragma unroll
            for (int i = 0; i < 4; i++)
                #pragma unroll
                for (int j = 0; j < 4; j++) acc[i][j] *= scale;
        }

        #pragma unroll
        for (int i = 0; i < 4; i++) {
            float rm = fmaxf(fmaxf(acc[i][0], acc[i][1]), fmaxf(acc[i][2], acc[i][3]));
            rm = fmaxf(rm, __shfl_xor_sync(0xffffffffu, rm, 1));
            rm = fmaxf(rm, __shfl_xor_sync(0xffffffffu, rm, 2));
            rm = fmaxf(rm, __shfl_xor_sync(0xffffffffu, rm, 4));
            rm = fmaxf(rm, __shfl_xor_sync(0xffffffffu, rm, 8));
            const float m_new = fmaxf(m_run[i], rm);
            const float corr = __expf(m_run[i] - m_new);
            float ls = 0.0f;
            #pragma unroll
            for (int j = 0; j < 4; j++) {
                acc[i][j] = __expf(acc[i][j] - m_new);
                ls += acc[i][j];
            }
            ls += __shfl_xor_sync(0xffffffffu, ls, 1);
            ls += __shfl_xor_sync(0xffffffffu, ls, 2);
            ls += __shfl_xor_sync(0xffffffffu, ls, 4);
            ls += __shfl_xor_sync(0xffffffffu, ls, 8);
            l_run[i] = l_run[i] * corr + ls;
            m_run[i] = m_new;
            #pragma unroll
            for (int j = 0; j < 4; j++) o[i][j] *= corr;
        }

        #pragma unroll
        for (int j = 0; j < 4; j++)
            #pragma unroll
            for (int i = 0; i < 4; i++)
                Ps[(tx * 4 + j) * PAD + ty * 4 + i] = acc[i][j];
        __syncthreads();

        #pragma unroll 16
        for (int k = 0; k < 64; k++) {
            float4 p4 = *(const float4*)&Ps[k * PAD + ty * 4];
            float4 v4 = *(const float4*)&Vs[k * PAD + tx * 4];
            float p[4] = {p4.x, p4.y, p4.z, p4.w};
            float vv[4] = {v4.x, v4.y, v4.z, v4.w};
            #pragma unroll
            for (int i = 0; i < 4; i++)
                #pragma unroll
                for (int j = 0; j < 4; j++)
                    o[i][j] += p[i] * vv[j];
        }
    }

    #pragma unroll
    for (int i = 0; i < 4; i++) {
        const float inv_l = 1.0f / l_run[i];
        float4 ov = make_float4(o[i][0] * inv_l, o[i][1] * inv_l,
                                o[i][2] * inv_l, o[i][3] * inv_l);
        *(float4*)&Y[base + (size_t)(qblk * 64 + ty * 4 + i) * D_MODEL + tx * 4] = ov;
    }
}

// ---------------- launch ----------------
extern "C" void kernel_launch(void* const* d_in, const int* in_sizes, int n_in,
                              void* d_out, int out_size)
{
    const float* x  = (const float*)d_in[0];
    const float* Wq = (const float*)d_in[1];
    const float* bq = (const float*)d_in[2];
    const float* Wk = (const float*)d_in[3];
    const float* bk = (const float*)d_in[4];
    const float* Wv = (const float*)d_in[5];
    const float* bv = (const float*)d_in[6];
    const float* Wp = (const float*)d_in[7];
    const float* bp = (const float*)d_in[8];
    float* out = (float*)d_out;

    float *q, *k, *v, *y;
    __nv_bfloat16 *xhi, *xlo, *yhi, *ylo, *whi, *wlo;
    cudaGetSymbolAddress((void**)&q, g_q);
    cudaGetSymbolAddress((void**)&k, g_k);
    cudaGetSymbolAddress((void**)&v, g_v);
    cudaGetSymbolAddress((void**)&y, g_y);
    cudaGetSymbolAddress((void**)&xhi, g_xhi);
    cudaGetSymbolAddress((void**)&xlo, g_xlo);
    cudaGetSymbolAddress((void**)&yhi, g_yhi);
    cudaGetSymbolAddress((void**)&ylo, g_ylo);
    cudaGetSymbolAddress((void**)&whi, g_whi);
    cudaGetSymbolAddress((void**)&wlo, g_wlo);

    cudaFuncSetAttribute(gemm_hmma,
                         cudaFuncAttributeMaxDynamicSharedMemorySize, GEMM_SMEM);
    cudaFuncSetAttribute(attn_v2,
                         cudaFuncAttributeMaxDynamicSharedMemorySize, ATTN_SMEM);

    const int WSZ = D_MODEL * D_MODEL;
    split_kernel<<<M_TOT * D_MODEL / 1024, 256>>>(
        (const float4*)x, (__nv_bfloat162*)xhi, (__nv_bfloat162*)xlo, M_TOT * D_MODEL / 4);
    split_kernel<<<WSZ / 1024, 256>>>(
        (const float4*)Wq, (__nv_bfloat162*)(whi + 0 * WSZ), (__nv_bfloat162*)(wlo + 0 * WSZ), WSZ / 4);
    split_kernel<<<WSZ / 1024, 256>>>(
        (const float4*)Wk, (__nv_bfloat162*)(whi + 1 * WSZ), (__nv_bfloat162*)(wlo + 1 * WSZ), WSZ / 4);
    split_kernel<<<WSZ / 1024, 256>>>(
        (const float4*)Wv, (__nv_bfloat162*)(whi + 2 * WSZ), (__nv_bfloat162*)(wlo + 2 * WSZ), WSZ / 4);
    split_kernel<<<WSZ / 1024, 256>>>(
        (const float4*)Wp, (__nv_bfloat162*)(whi + 3 * WSZ), (__nv_bfloat162*)(wlo + 3 * WSZ), WSZ / 4);

    dim3 ggrid(D_MODEL / 128, M_TOT / 128);   // (8, 32)
    gemm_hmma<<<ggrid, 256, GEMM_SMEM>>>(xhi, xlo, whi + 0 * WSZ, wlo + 0 * WSZ, bq, q);
    gemm_hmma<<<ggrid, 256, GEMM_SMEM>>>(xhi, xlo, whi + 1 * WSZ, wlo + 1 * WSZ, bk, k);
    gemm_hmma<<<ggrid, 256, GEMM_SMEM>>>(xhi, xlo, whi + 2 * WSZ, wlo + 2 * WSZ, bv, v);

    attn_v2<<<dim3(SEQ / 64, BATCH * N_HEADS), 256, ATTN_SMEM>>>(q, k, v, y);

    split_kernel<<<M_TOT * D_MODEL / 1024, 256>>>(
        (const float4*)y, (__nv_bfloat162*)yhi, (__nv_bfloat162*)ylo, M_TOT * D_MODEL / 4);
    gemm_hmma<<<ggrid, 256, GEMM_SMEM>>>(yhi, ylo, whi + 3 * WSZ, wlo + 3 * WSZ, bp, out);
}

// round 5
// speedup vs baseline: 6.7813x; 1.9176x over previous
#include <cuda_runtime.h>
#include <cuda_bf16.h>
#include <cstdint>

#define D_MODEL  1024
#define N_HEADS  16
#define HEAD_DIM 64
#define BATCH    2
#define SEQ      2048
#define M_TOT    (BATCH * SEQ)   // 4096

// ---------------- scratch ----------------
__device__ __align__(1024) __nv_bfloat16 g_qhi[M_TOT * D_MODEL];
__device__ __align__(1024) __nv_bfloat16 g_qlo[M_TOT * D_MODEL];
__device__ __align__(1024) __nv_bfloat16 g_khi[M_TOT * D_MODEL];
__device__ __align__(1024) __nv_bfloat16 g_klo[M_TOT * D_MODEL];
__device__ __align__(1024) __nv_bfloat16 g_vhi[M_TOT * D_MODEL];
__device__ __align__(1024) __nv_bfloat16 g_vlo[M_TOT * D_MODEL];
__device__ __align__(1024) __nv_bfloat16 g_yhi[M_TOT * D_MODEL];
__device__ __align__(1024) __nv_bfloat16 g_ylo[M_TOT * D_MODEL];
__device__ __align__(1024) __nv_bfloat16 g_xhi[M_TOT * D_MODEL];
__device__ __align__(1024) __nv_bfloat16 g_xlo[M_TOT * D_MODEL];
__device__ __align__(1024) __nv_bfloat16 g_whi[4u * D_MODEL * D_MODEL];
__device__ __align__(1024) __nv_bfloat16 g_wlo[4u * D_MODEL * D_MODEL];

// ---------------- helpers ----------------
__device__ __forceinline__ uint32_t smem_u32(const void* p) {
    uint32_t a;
    asm("{ .reg .u64 t; cvta.to.shared.u64 t, %1; cvt.u32.u64 %0, t; }" : "=r"(a) : "l"(p));
    return a;
}
__device__ __forceinline__ uint32_t swz128(uint32_t off) { return off ^ ((off >> 3) & 0x70); }
__device__ __forceinline__ void cp16(uint32_t s, const void* g) {
    asm volatile("cp.async.cg.shared.global [%0], [%1], 16;" :: "r"(s), "l"(g));
}
#define CP_COMMIT() asm volatile("cp.async.commit_group;" ::: "memory")
#define CP_WAIT(n)  asm volatile("cp.async.wait_group %0;" :: "n"(n) : "memory")

__device__ __forceinline__ void ldsm4(uint32_t r[4], uint32_t addr) {
    asm volatile("ldmatrix.sync.aligned.m8n8.x4.shared.b16 {%0,%1,%2,%3}, [%4];"
                 : "=r"(r[0]), "=r"(r[1]), "=r"(r[2]), "=r"(r[3]) : "r"(addr));
}
__device__ __forceinline__ void ldsm4t(uint32_t r[4], uint32_t addr) {
    asm volatile("ldmatrix.sync.aligned.m8n8.x4.trans.shared.b16 {%0,%1,%2,%3}, [%4];"
                 : "=r"(r[0]), "=r"(r[1]), "=r"(r[2]), "=r"(r[3]) : "r"(addr));
}
__device__ __forceinline__ void mma_bf16(float d[4], const uint32_t a[4], const uint32_t b[2]) {
    asm volatile(
        "mma.sync.aligned.m16n8k16.row.col.f32.bf16.bf16.f32 "
        "{%0,%1,%2,%3}, {%4,%5,%6,%7}, {%8,%9}, {%0,%1,%2,%3};"
        : "+f"(d[0]), "+f"(d[1]), "+f"(d[2]), "+f"(d[3])
        : "r"(a[0]), "r"(a[1]), "r"(a[2]), "r"(a[3]), "r"(b[0]), "r"(b[1]));
}
__device__ __forceinline__ uint32_t pack_bf16x2(float lo, float hi) {
    uint32_t r;
    asm("cvt.rn.bf16x2.f32 %0, %1, %2;" : "=r"(r) : "f"(hi), "f"(lo));
    return r;
}
__device__ __forceinline__ float bf16_round(float x) {
    return __bfloat162float(__float2bfloat16(x));
}

// ---------------- split fp32 -> bf16 hi/lo ----------------
__global__ __launch_bounds__(256) void split_kernel(
    const float4* __restrict__ x, __nv_bfloat162* __restrict__ hi,
    __nv_bfloat162* __restrict__ lo, int n4)
{
    int i = blockIdx.x * 256 + threadIdx.x;
    if (i >= n4) return;
    float4 v = x[i];
    __nv_bfloat16 h0 = __float2bfloat16(v.x), h1 = __float2bfloat16(v.y);
    __nv_bfloat16 h2 = __float2bfloat16(v.z), h3 = __float2bfloat16(v.w);
    hi[2 * i + 0] = __halves2bfloat162(h0, h1);
    hi[2 * i + 1] = __halves2bfloat162(h2, h3);
    lo[2 * i + 0] = __halves2bfloat162(
        __float2bfloat16(v.x - __bfloat162float(h0)),
        __float2bfloat16(v.y - __bfloat162float(h1)));
    lo[2 * i + 1] = __halves2bfloat162(
        __float2bfloat16(v.z - __bfloat162float(h2)),
        __float2bfloat16(v.w - __bfloat162float(h3)));
}

// ---------------- HMMA split-bf16 GEMM ----------------
#define T_B    16384
#define STG_B  (4 * T_B)
#define GEMM_SMEM (2 * STG_B)
#define KCHUNKS (D_MODEL / 64)

__device__ __forceinline__ void load_stage(
    uint32_t sbase, const __nv_bfloat16* a0, const __nv_bfloat16* a1,
    const __nv_bfloat16* b0, const __nv_bfloat16* b1, int kc, int tid)
{
    const __nv_bfloat16* gs[4] = {a0, a1, b0, b1};
    #pragma unroll
    for (int t = 0; t < 4; t++) {
        uint32_t tb = sbase + t * T_B;
        const __nv_bfloat16* g = gs[t] + kc * 64;
        #pragma unroll
        for (int i = 0; i < 4; i++) {
            int u = i * 256 + tid;
            int r = u >> 3, c8 = u & 7;
            cp16(tb + swz128(r * 128 + c8 * 16), g + (size_t)r * D_MODEL + c8 * 8);
        }
    }
}

template <bool SPLIT>
__global__ __launch_bounds__(256) void gemm_hmma(
    const __nv_bfloat16* __restrict__ Ahi, const __nv_bfloat16* __restrict__ Alo,
    const __nv_bfloat16* __restrict__ Bhi, const __nv_bfloat16* __restrict__ Blo,
    const float* __restrict__ bias, float* __restrict__ C,
    __nv_bfloat16* __restrict__ Chi, __nv_bfloat16* __restrict__ Clo)
{
    extern __shared__ __align__(1024) char smem[];
    const uint32_t sb = smem_u32(smem);
    const int tid = threadIdx.x;
    const int wid = tid >> 5, lane = tid & 31;
    const int n0 = blockIdx.x * 128, m0 = blockIdx.y * 128;
    const int wm = (wid >> 1) * 32;
    const int wn = (wid & 1) * 64;
    const int gid = lane >> 2, tig = lane & 3;

    const __nv_bfloat16* a0 = Ahi + (size_t)m0 * D_MODEL;
    const __nv_bfloat16* a1 = Alo + (size_t)m0 * D_MODEL;
    const __nv_bfloat16* b0 = Bhi + (size_t)n0 * D_MODEL;
    const __nv_bfloat16* b1 = Blo + (size_t)n0 * D_MODEL;

    const int a_row  = wm + (lane & 15);
    const int a_byte = ((lane >> 4) & 1) * 16;
    const int b_row  = wn + ((lane >> 4) & 1) * 8 + (lane & 7);
    const int b_byte = ((lane >> 3) & 1) * 16;

    float d[2][8][4];
    #pragma unroll
    for (int i = 0; i < 2; i++)
        #pragma unroll
        for (int j = 0; j < 8; j++)
            #pragma unroll
            for (int c = 0; c < 4; c++) d[i][j][c] = 0.0f;

    load_stage(sb, a0, a1, b0, b1, 0, tid);
    CP_COMMIT();

    for (int kc = 0; kc < KCHUNKS; kc++) {
        const uint32_t st = sb + (kc & 1) * STG_B;
        __syncthreads();
        if (kc + 1 < KCHUNKS) {
            load_stage(sb + ((kc + 1) & 1) * STG_B, a0, a1, b0, b1, kc + 1, tid);
            CP_COMMIT();
            CP_WAIT(1);
        } else {
            CP_WAIT(0);
        }
        __syncthreads();

        #pragma unroll
        for (int ks = 0; ks < 4; ks++) {
            uint32_t ah[2][4], al[2][4];
            #pragma unroll
            for (int am = 0; am < 2; am++) {
                uint32_t off = swz128((uint32_t)(a_row + am * 16) * 128 + a_byte + ks * 32);
                ldsm4(ah[am], st + off);
                ldsm4(al[am], st + T_B + off);
            }
            uint32_t bh[8][2], bl[8][2];
            #pragma unroll
            for (int pr = 0; pr < 4; pr++) {
                uint32_t off = swz128((uint32_t)(b_row + pr * 16) * 128 + b_byte + ks * 32);
                uint32_t r[4];
                ldsm4(r, st + 2 * T_B + off);
                bh[2 * pr][0] = r[0]; bh[2 * pr][1] = r[1];
                bh[2 * pr + 1][0] = r[2]; bh[2 * pr + 1][1] = r[3];
                ldsm4(r, st + 3 * T_B + off);
                bl[2 * pr][0] = r[0]; bl[2 * pr][1] = r[1];
                bl[2 * pr + 1][0] = r[2]; bl[2 * pr + 1][1] = r[3];
            }
            #pragma unroll
            for (int am = 0; am < 2; am++)
                #pragma unroll
                for (int bn = 0; bn < 8; bn++) {
                    mma_bf16(d[am][bn], ah[am], bh[bn]);
                    mma_bf16(d[am][bn], ah[am], bl[bn]);
                    mma_bf16(d[am][bn], al[am], bh[bn]);
                }
        }
    }

    #pragma unroll
    for (int am = 0; am < 2; am++) {
        const int row = m0 + wm + am * 16 + gid;
        #pragma unroll
        for (int bn = 0; bn < 8; bn++) {
            const int col = n0 + wn + bn * 8 + tig * 2;
            const float bv0 = __ldg(&bias[col]);
            const float bv1 = __ldg(&bias[col + 1]);
            float v0 = d[am][bn][0] + bv0, v1 = d[am][bn][1] + bv1;
            float v2 = d[am][bn][2] + bv0, v3 = d[am][bn][3] + bv1;
            if (SPLIT) {
                *(uint32_t*)&Chi[(size_t)row * D_MODEL + col] = pack_bf16x2(v0, v1);
                *(uint32_t*)&Clo[(size_t)row * D_MODEL + col] =
                    pack_bf16x2(v0 - bf16_round(v0), v1 - bf16_round(v1));
                *(uint32_t*)&Chi[(size_t)(row + 8) * D_MODEL + col] = pack_bf16x2(v2, v3);
                *(uint32_t*)&Clo[(size_t)(row + 8) * D_MODEL + col] =
                    pack_bf16x2(v2 - bf16_round(v2), v3 - bf16_round(v3));
            } else {
                *(float2*)&C[(size_t)row * D_MODEL + col] = make_float2(v0, v1);
                *(float2*)&C[(size_t)(row + 8) * D_MODEL + col] = make_float2(v2, v3);
            }
        }
    }
}

// ---------------- HMMA flash attention (split-bf16) ----------------
// CTA: 128 queries, 8 warps (warp w owns rows w*16..w*16+15), 64-key tiles,
// double-buffered cp.async K/V hi/lo. P kept in registers (accum->A-frag map).
#define AQ 128
#define KV_STG 32768                    // khi,klo,vhi,vlo @ 8192 each
#define ATT_SMEM (2 * AQ * 128 + 2 * KV_STG)   // 98304

__global__ __launch_bounds__(256) void attn_hmma(
    const __nv_bfloat16* __restrict__ Qhi, const __nv_bfloat16* __restrict__ Qlo,
    const __nv_bfloat16* __restrict__ Khi, const __nv_bfloat16* __restrict__ Klo,
    const __nv_bfloat16* __restrict__ Vhi, const __nv_bfloat16* __restrict__ Vlo,
    __nv_bfloat16* __restrict__ Yhi, __nv_bfloat16* __restrict__ Ylo)
{
    extern __shared__ __align__(1024) char smA[];
    const uint32_t sb = smem_u32(smA);
    const int tid = threadIdx.x, wid = tid >> 5, lane = tid & 31;
    const int gid = lane >> 2, tig = lane & 3;
    const int qblk = blockIdx.x, bh = blockIdx.y;
    const int b = bh >> 4, h = bh & 15;
    const size_t base = ((size_t)b * SEQ) * D_MODEL + (size_t)h * HEAD_DIM;

    const uint32_t sQh = sb;
    const uint32_t sQl = sb + AQ * 128;
    const uint32_t sKV = sb + 2 * AQ * 128;

    // load Q hi/lo (128 rows x 128B each)
    {
        const __nv_bfloat16* q0 = Qhi + base + (size_t)qblk * AQ * D_MODEL;
        const __nv_bfloat16* q1 = Qlo + base + (size_t)qblk * AQ * D_MODEL;
        #pragma unroll
        for (int i = 0; i < 4; i++) {
            int u = i * 256 + tid;
            int r = u >> 3, c = u & 7;
            cp16(sQh + swz128(r * 128 + c * 16), q0 + (size_t)r * D_MODEL + c * 8);
            cp16(sQl + swz128(r * 128 + c * 16), q1 + (size_t)r * D_MODEL + c * 8);
        }
    }
    CP_COMMIT();

    const int nkt = 2 * qblk + 2;

    // prefetch KV tile 0
    {
        const __nv_bfloat16* srcs[4] = {Khi + base, Klo + base, Vhi + base, Vlo + base};
        #pragma unroll
        for (int t = 0; t < 4; t++)
            #pragma unroll
            for (int i = 0; i < 2; i++) {
                int u = i * 256 + tid;
                int r = u >> 3, c = u & 7;
                cp16(sKV + t * 8192 + swz128(r * 128 + c * 16),
                     srcs[t] + (size_t)r * D_MODEL + c * 8);
            }
    }
    CP_COMMIT();
    CP_WAIT(1);          // Q complete
    __syncthreads();

    // Q fragments (persist across key tiles)
    uint32_t qh[4][4], ql[4][4];
    {
        const int ar = wid * 16 + (lane & 15);
        const int ab = ((lane >> 4) & 1) * 16;
        #pragma unroll
        for (int ks = 0; ks < 4; ks++) {
            ldsm4(qh[ks], sQh + swz128((uint32_t)ar * 128 + ab + ks * 32));
            ldsm4(ql[ks], sQl + swz128((uint32_t)ar * 128 + ab + ks * 32));
        }
    }

    float o[8][4];
    #pragma unroll
    for (int nt = 0; nt < 8; nt++)
        #pragma unroll
        for (int j = 0; j < 4; j++) o[nt][j] = 0.0f;
    float m0 = -1e30f, m1 = -1e30f, l0 = 0.0f, l1 = 0.0f;

    const int qr0 = qblk * AQ + wid * 16 + gid;       // rows qr0, qr0+8
    const int row_min = qblk * AQ + wid * 16;
    const int row_max = row_min + 15;

    const int sbr = ((lane >> 4) & 1) * 8 + (lane & 7);
    const int sbb = ((lane >> 3) & 1) * 16;
    const int vrr = lane & 15;
    const int vbb = ((lane >> 4) & 1) * 16;

    for (int kt = 0; kt < nkt; kt++) {
        const uint32_t st = sKV + (uint32_t)(kt & 1) * KV_STG;
        __syncthreads();        // all warps done with the buffer we're about to fill
        if (kt + 1 < nkt) {
            const size_t koff = base + (size_t)(kt + 1) * 64 * D_MODEL;
            const __nv_bfloat16* srcs[4] = {Khi + koff, Klo + koff, Vhi + koff, Vlo + koff};
            const uint32_t dst = sKV + (uint32_t)((kt + 1) & 1) * KV_STG;
            #pragma unroll
            for (int t = 0; t < 4; t++)
                #pragma unroll
                for (int i = 0; i < 2; i++) {
                    int u = i * 256 + tid;
                    int r = u >> 3, c = u & 7;
                    cp16(dst + t * 8192 + swz128(r * 128 + c * 16),
                         srcs[t] + (size_t)r * D_MODEL + c * 8);
                }
            CP_COMMIT();
            CP_WAIT(1);
        } else {
            CP_WAIT(0);
        }
        __syncthreads();

        if (kt * 64 > row_max) continue;    // fully masked for this warp

        // ---- S = Q K^T ----
        float s[8][4];
        #pragma unroll
        for (int nt = 0; nt < 8; nt++)
            #pragma unroll
            for (int j = 0; j < 4; j++) s[nt][j] = 0.0f;

        #pragma unroll
        for (int ks = 0; ks < 4; ks++) {
            #pragma unroll
            for (int np = 0; np < 4; np++) {
                uint32_t off = swz128((uint32_t)(np * 16 + sbr) * 128 + sbb + ks * 32);
                uint32_t rh[4], rl[4];
                ldsm4(rh, st + off);              // Khi
                ldsm4(rl, st + 8192 + off);       // Klo
                uint32_t bh0[2] = {rh[0], rh[1]}, bh1[2] = {rh[2], rh[3]};
                uint32_t bl0[2] = {rl[0], rl[1]}, bl1[2] = {rl[2], rl[3]};
                mma_bf16(s[2 * np],     qh[ks], bh0);
                mma_bf16(s[2 * np],     qh[ks], bl0);
                mma_bf16(s[2 * np],     ql[ks], bh0);
                mma_bf16(s[2 * np + 1], qh[ks], bh1);
                mma_bf16(s[2 * np + 1], qh[ks], bl1);
                mma_bf16(s[2 * np + 1], ql[ks], bh1);
            }
        }

        // scale + causal mask
        const bool need_mask = (kt * 64 + 63 > row_min);
        #pragma unroll
        for (int nt = 0; nt < 8; nt++) {
            #pragma unroll
            for (int j = 0; j < 4; j++) s[nt][j] *= 0.125f;
            if (need_mask) {
                const int kc = kt * 64 + nt * 8 + 2 * tig;
                if (kc     > qr0)     s[nt][0] = -1e30f;
                if (kc + 1 > qr0)     s[nt][1] = -1e30f;
                if (kc     > qr0 + 8) s[nt][2] = -1e30f;
                if (kc + 1 > qr0 + 8) s[nt][3] = -1e30f;
            }
        }

        // ---- online softmax ----
        float mx0 = -1e30f, mx1 = -1e30f;
        #pragma unroll
        for (int nt = 0; nt < 8; nt++) {
            mx0 = fmaxf(mx0, fmaxf(s[nt][0], s[nt][1]));
            mx1 = fmaxf(mx1, fmaxf(s[nt][2], s[nt][3]));
        }
        mx0 = fmaxf(mx0, __shfl_xor_sync(0xffffffffu, mx0, 1));
        mx0 = fmaxf(mx0, __shfl_xor_sync(0xffffffffu, mx0, 2));
        mx1 = fmaxf(mx1, __shfl_xor_sync(0xffffffffu, mx1, 1));
        mx1 = fmaxf(mx1, __shfl_xor_sync(0xffffffffu, mx1, 2));
        const float nm0 = fmaxf(m0, mx0), nm1 = fmaxf(m1, mx1);
        const float c0 = __expf(m0 - nm0), c1 = __expf(m1 - nm1);
        m0 = nm0; m1 = nm1;

        uint32_t pAh[8], pBh[8], pAl[8], pBl[8];
        float la0 = 0.0f, la1 = 0.0f;
        #pragma unroll
        for (int nt = 0; nt < 8; nt++) {
            float p0 = __expf(s[nt][0] - m0), p1 = __expf(s[nt][1] - m0);
            float p2 = __expf(s[nt][2] - m1), p3 = __expf(s[nt][3] - m1);
            la0 += p0 + p1; la1 += p2 + p3;
            pAh[nt] = pack_bf16x2(p0, p1);
            pAl[nt] = pack_bf16x2(p0 - bf16_round(p0), p1 - bf16_round(p1));
            pBh[nt] = pack_bf16x2(p2, p3);
            pBl[nt] = pack_bf16x2(p2 - bf16_round(p2), p3 - bf16_round(p3));
        }
        la0 += __shfl_xor_sync(0xffffffffu, la0, 1);
        la0 += __shfl_xor_sync(0xffffffffu, la0, 2);
        la1 += __shfl_xor_sync(0xffffffffu, la1, 1);
        la1 += __shfl_xor_sync(0xffffffffu, la1, 2);
        l0 = l0 * c0 + la0;
        l1 = l1 * c1 + la1;
        #pragma unroll
        for (int nt = 0; nt < 8; nt++) {
            o[nt][0] *= c0; o[nt][1] *= c0;
            o[nt][2] *= c1; o[nt][3] *= c1;
        }

        // ---- O += P V ----
        #pragma unroll
        for (int kk = 0; kk < 4; kk++) {
            uint32_t aH[4] = {pAh[2 * kk], pBh[2 * kk], pAh[2 * kk + 1], pBh[2 * kk + 1]};
            uint32_t aL[4] = {pAl[2 * kk], pBl[2 * kk], pAl[2 * kk + 1], pBl[2 * kk + 1]};
            #pragma unroll
            for (int np = 0; np < 4; np++) {
                uint32_t off = swz128((uint32_t)(kk * 16 + vrr) * 128 + vbb + np * 32);
                uint32_t rh[4], rl[4];
                ldsm4t(rh, st + 16384 + off);     // Vhi
                ldsm4t(rl, st + 24576 + off);     // Vlo
                uint32_t b0h[2] = {rh[0], rh[1]}, b1h[2] = {rh[2], rh[3]};
                uint32_t b0l[2] = {rl[0], rl[1]}, b1l[2] = {rl[2], rl[3]};
                mma_bf16(o[2 * np],     aH, b0h);
                mma_bf16(o[2 * np],     aH, b0l);
                mma_bf16(o[2 * np],     aL, b0h);
                mma_bf16(o[2 * np + 1], aH, b1h);
                mma_bf16(o[2 * np + 1], aH, b1l);
                mma_bf16(o[2 * np + 1], aL, b1h);
            }
        }
    }

    // ---- epilogue: normalize, split to bf16 hi/lo, store ----
    const float i0 = 1.0f / l0, i1 = 1.0f / l1;
    const size_t r0a = base + (size_t)qr0 * D_MODEL;
    const size_t r1a = base + (size_t)(qr0 + 8) * D_MODEL;
    #pragma unroll
    for (int nt = 0; nt < 8; nt++) {
        const int col = nt * 8 + 2 * tig;
        float v0 = o[nt][0] * i0, v1 = o[nt][1] * i0;
        float v2 = o[nt][2] * i1, v3 = o[nt][3] * i1;
        *(uint32_t*)&Yhi[r0a + col] = pack_bf16x2(v0, v1);
        *(uint32_t*)&Ylo[r0a + col] = pack_bf16x2(v0 - bf16_round(v0), v1 - bf16_round(v1));
        *(uint32_t*)&Yhi[r1a + col] = pack_bf16x2(v2, v3);
        *(uint32_t*)&Ylo[r1a + col] = pack_bf16x2(v2 - bf16_round(v2), v3 - bf16_round(v3));
    }
}

// ---------------- launch ----------------
extern "C" void kernel_launch(void* const* d_in, const int* in_sizes, int n_in,
                              void* d_out, int out_size)
{
    const float* x  = (const float*)d_in[0];
    const float* Wq = (const float*)d_in[1];
    const float* bq = (const float*)d_in[2];
    const float* Wk = (const float*)d_in[3];
    const float* bk = (const float*)d_in[4];
    const float* Wv = (const float*)d_in[5];
    const float* bv = (const float*)d_in[6];
    const float* Wp = (const float*)d_in[7];
    const float* bp = (const float*)d_in[8];
    float* out = (float*)d_out;

    __nv_bfloat16 *qhi, *qlo, *khi, *klo, *vhi, *vlo, *yhi, *ylo, *xhi, *xlo, *whi, *wlo;
    cudaGetSymbolAddress((void**)&qhi, g_qhi);
    cudaGetSymbolAddress((void**)&qlo, g_qlo);
    cudaGetSymbolAddress((void**)&khi, g_khi);
    cudaGetSymbolAddress((void**)&klo, g_klo);
    cudaGetSymbolAddress((void**)&vhi, g_vhi);
    cudaGetSymbolAddress((void**)&vlo, g_vlo);
    cudaGetSymbolAddress((void**)&yhi, g_yhi);
    cudaGetSymbolAddress((void**)&ylo, g_ylo);
    cudaGetSymbolAddress((void**)&xhi, g_xhi);
    cudaGetSymbolAddress((void**)&xlo, g_xlo);
    cudaGetSymbolAddress((void**)&whi, g_whi);
    cudaGetSymbolAddress((void**)&wlo, g_wlo);

    cudaFuncSetAttribute(gemm_hmma<true>,
                         cudaFuncAttributeMaxDynamicSharedMemorySize, GEMM_SMEM);
    cudaFuncSetAttribute(gemm_hmma<false>,
                         cudaFuncAttributeMaxDynamicSharedMemorySize, GEMM_SMEM);
    cudaFuncSetAttribute(attn_hmma,
                         cudaFuncAttributeMaxDynamicSharedMemorySize, ATT_SMEM);

    const int WSZ = D_MODEL * D_MODEL;
    split_kernel<<<M_TOT * D_MODEL / 1024, 256>>>(
        (const float4*)x, (__nv_bfloat162*)xhi, (__nv_bfloat162*)xlo, M_TOT * D_MODEL / 4);
    split_kernel<<<WSZ / 1024, 256>>>(
        (const float4*)Wq, (__nv_bfloat162*)(whi + 0 * WSZ), (__nv_bfloat162*)(wlo + 0 * WSZ), WSZ / 4);
    split_kernel<<<WSZ / 1024, 256>>>(
        (const float4*)Wk, (__nv_bfloat162*)(whi + 1 * WSZ), (__nv_bfloat162*)(wlo + 1 * WSZ), WSZ / 4);
    split_kernel<<<WSZ / 1024, 256>>>(
        (const float4*)Wv, (__nv_bfloat162*)(whi + 2 * WSZ), (__nv_bfloat162*)(wlo + 2 * WSZ), WSZ / 4);
    split_kernel<<<WSZ / 1024, 256>>>(
        (const float4*)Wp, (__nv_bfloat162*)(whi + 3 * WSZ), (__nv_bfloat162*)(wlo + 3 * WSZ), WSZ / 4);

    dim3 ggrid(D_MODEL / 128, M_TOT / 128);   // (8, 32)
    gemm_hmma<true><<<ggrid, 256, GEMM_SMEM>>>(xhi, xlo, whi + 0 * WSZ, wlo + 0 * WSZ, bq,
                                               nullptr, qhi, qlo);
    gemm_hmma<true><<<ggrid, 256, GEMM_SMEM>>>(xhi, xlo, whi + 1 * WSZ, wlo + 1 * WSZ, bk,
                                               nullptr, khi, klo);
    gemm_hmma<true><<<ggrid, 256, GEMM_SMEM>>>(xhi, xlo, whi + 2 * WSZ, wlo + 2 * WSZ, bv,
                                               nullptr, vhi, vlo);

    attn_hmma<<<dim3(SEQ / AQ, BATCH * N_HEADS), 256, ATT_SMEM>>>(
        qhi, qlo, khi, klo, vhi, vlo, yhi, ylo);

    gemm_hmma<false><<<ggrid, 256, GEMM_SMEM>>>(yhi, ylo, whi + 3 * WSZ, wlo + 3 * WSZ, bp,
                                                out, nullptr, nullptr);
}